// round 14
// baseline (speedup 1.0000x reference)
#include <cuda_runtime.h>
#include <cuda_bf16.h>
#include <cstdint>

// ChaosModulator: per-channel nonlinear recurrence over t.
//   sigma = 3.5*z*(1-z) + 0.5*x
//   z'    = 0.5*z + 0.5*sigmoid(2*sigma)     (clip(0,1) is a provable no-op)
//   u     = 0.5*x + (z' - 0.5)
//
// R14 = R10 skeleton + ILP-2. R10 is latency-bound on the per-thread serial
// z-chain (~48 cyc/step, ~8 instr/link -> no pipe saturates). Each lane now
// advances TWO independent chains (rows lane and lane+32 = same chunk of two
// channels), doubling issuable work per chain-link and per-warp byte rate.
// Warp owns 8 channels x 8 chunks = 64 rows = contiguous 128KB x-span
// (row r = ch_local*8 + s -> addr r*CHUNK, T = 8*CHUNK). Warmup fraction
// unchanged (1/8). Simple LDG->STS staging (R13 showed cp.async costs more
// than it buys), XOR float4 swizzle, __syncwarp only, WARM=64 from z=0.5.

#define WARM  64
#define TS    32

__device__ __forceinline__ float ex2_approx(float v) {
    float y; asm("ex2.approx.f32 %0, %1;" : "=f"(y) : "f"(v)); return y;
}
__device__ __forceinline__ float rcp_approx(float v) {
    float y; asm("rcp.approx.f32 %0, %1;" : "=f"(y) : "f"(v)); return y;
}

// sigma_tilde = -2*log2(e)*sigma = K1*(z - z^2) + K2*x
#define K1 (-10.098865286222744f)  /* -7 * log2(e) */
#define K2 (-1.4426950408889634f)  /* -1 * log2(e) */

__device__ __forceinline__ float step_z(float z, float xx) {
    float p  = fmaf(-z, z, z);          // z - z^2
    float tt = fmaf(K1, p, K2 * xx);
    float e  = ex2_approx(tt);
    float r  = rcp_approx(1.0f + e);    // sigmoid(2*sigma)
    return fmaf(0.5f, r, 0.5f * z);
}

__global__ void __launch_bounds__(128, 7)
chaos_kernel(const float* __restrict__ x,
             const float* __restrict__ z0,
             float* __restrict__ u,
             int n_ch, int T)
{
    // Per-warp slab: 64 rows x 8 float4 (128B row stride) = 8KB; 32KB/block.
    __shared__ float4 sbuf[4][64][8];

    const int tid  = threadIdx.x;
    const int wid  = tid >> 5;
    const int lane = tid & 31;

    const int CHUNK = T >> 3;                 // 512 (S = 8 chunks)
    const int NT    = CHUNK / TS;             // 16 tiles

    // Warp owns channels [ch0, ch0+8): one contiguous 128KB span of x.
    const int ch0 = (blockIdx.x * 4 + wid) * 8;
    const char* __restrict__ gx = (const char*)(x + (size_t)ch0 * T);
    char* __restrict__       gu = (char*)(u + (size_t)ch0 * T);

    const int l3 = lane >> 3;                 // 0..3  (loader row group)
    const int c4 = lane & 7;                  // float4 column group

    float4 (*sb)[8] = sbuf[wid];

    // Loader gmem byte offset: row r = l3 + 4j (j=0..15), +4 rows = +4*CHUNK.
    const uint32_t off0 = (uint32_t)((l3 * CHUNK + c4 * 4) * 4);
    const uint32_t JSTR = (uint32_t)(4 * CHUNK * 4);   // 8192

    // Compute role: lane owns rows lane and lane+32.
    //   row lane   -> channel ch0 + (lane>>3),     chunk s = lane&7
    //   row lane+32-> channel ch0 + 4 + (lane>>3), chunk s = lane&7 (same!)
    const int s    = lane & 7;
    const int ckey = lane & 7;                // swizzle key (r&7), same both rows
    float za = (s == 0) ? z0[ch0 + (lane >> 3)]     : 0.5f;
    float zb = (s == 0) ? z0[ch0 + 4 + (lane >> 3)] : 0.5f;

    // ---- Warmup: 2 tiles of 32 steps (chunk-0 rows skip) ----
    for (int w = 0; w < WARM / TS; ++w) {
        const int tb = (-WARM + w * TS) * 4;          // byte offset in t
#pragma unroll
        for (int j = 0; j < 16; ++j) {
            int r   = l3 + 4 * j;                     // row 0..63
            int key = l3 | ((j & 1) << 2);            // r&7
            if (key != 0) {
                float4 v = *(const float4*)(gx + off0 + tb + j * JSTR);
                sb[r][c4 ^ key] = v;
            }
        }
        __syncwarp();
        if (s != 0) {
#pragma unroll
            for (int c = 0; c < 8; ++c) {
                float4 va = sb[lane][c ^ ckey];
                float4 vb = sb[lane + 32][c ^ ckey];
                za = step_z(za, va.x); zb = step_z(zb, vb.x);
                za = step_z(za, va.y); zb = step_z(zb, vb.y);
                za = step_z(za, va.z); zb = step_z(zb, vb.z);
                za = step_z(za, va.w); zb = step_z(zb, vb.w);
            }
        }
        __syncwarp();
    }

    // ---- Main: per-tile load -> compute in place -> store, warp-private ----
    for (int tile = 0; tile < NT; ++tile) {
        const uint32_t tb = (uint32_t)(tile * TS * 4);

#pragma unroll
        for (int j = 0; j < 16; ++j) {
            int r   = l3 + 4 * j;
            int key = l3 | ((j & 1) << 2);
            float4 v = *(const float4*)(gx + off0 + tb + j * JSTR);
            sb[r][c4 ^ key] = v;
        }
        __syncwarp();

#pragma unroll
        for (int c = 0; c < 8; ++c) {
            int ia = lane, ib = lane + 32;
            float4 va = sb[ia][c ^ ckey];
            float4 vb = sb[ib][c ^ ckey];
            float4 oa, ob; float ha, hb;
            ha = fmaf(0.5f, va.x, -0.5f); hb = fmaf(0.5f, vb.x, -0.5f);
            za = step_z(za, va.x);        zb = step_z(zb, vb.x);
            oa.x = ha + za;               ob.x = hb + zb;
            ha = fmaf(0.5f, va.y, -0.5f); hb = fmaf(0.5f, vb.y, -0.5f);
            za = step_z(za, va.y);        zb = step_z(zb, vb.y);
            oa.y = ha + za;               ob.y = hb + zb;
            ha = fmaf(0.5f, va.z, -0.5f); hb = fmaf(0.5f, vb.z, -0.5f);
            za = step_z(za, va.z);        zb = step_z(zb, vb.z);
            oa.z = ha + za;               ob.z = hb + zb;
            ha = fmaf(0.5f, va.w, -0.5f); hb = fmaf(0.5f, vb.w, -0.5f);
            za = step_z(za, va.w);        zb = step_z(zb, vb.w);
            oa.w = ha + za;               ob.w = hb + zb;
            sb[ia][c ^ ckey] = oa;
            sb[ib][c ^ ckey] = ob;
        }
        __syncwarp();

#pragma unroll
        for (int j = 0; j < 16; ++j) {
            int r   = l3 + 4 * j;
            int key = l3 | ((j & 1) << 2);
            float4 v = sb[r][c4 ^ key];
            *(float4*)(gu + off0 + tb + j * JSTR) = v;
        }
        __syncwarp();                        // protect smem before next STS
    }
}

extern "C" void kernel_launch(void* const* d_in, const int* in_sizes, int n_in,
                              void* d_out, int out_size)
{
    const float* x  = (const float*)d_in[0];   // (b, c, t) f32
    const float* z0 = (const float*)d_in[1];   // (b, c)    f32
    float* u = (float*)d_out;

    int n_ch = in_sizes[1];            // b*c = 16384
    int T    = in_sizes[0] / n_ch;     // 4096

    int grid = n_ch / 32;              // 32 channels per 128-thread block
    chaos_kernel<<<grid, 128>>>(x, z0, u, n_ch, T);
}

// round 15
// speedup vs baseline: 1.4839x; 1.4839x over previous
#include <cuda_runtime.h>
#include <cuda_bf16.h>
#include <cstdint>

// ChaosModulator: per-channel nonlinear recurrence over t.
//   sigma = 3.5*z*(1-z) + 0.5*x
//   z'    = 0.5*z + 0.5*sigmoid(2*sigma)     (clip(0,1) is a provable no-op)
//   u     = 0.5*x + (z' - 0.5)
//
// R15 = R10 skeleton with TS=64 + single-slab cp.async staging.
// R10 was limited by outstanding bytes per SM (Little's law: ~19KB avg vs
// ~17.6KB needed -> DRAM stuck at 66%). TS=64 doubles the per-warp load
// batch to 8KB, and cp.async.cg issues all 16 copies with no data registers
// (LDG staging waves at ~8 by reg pressure). Single slab: no pipeline regs,
// no double-buffer smem -> occupancy stays at R10's grid-limited 6.9
// blocks/SM (R13/R14 falsified resource-hungry variants).
// Warp owns 4 channels x 8 chunks = 32 rows = contiguous 64KB x-span
// (row r -> gmem r*CHUNK; chunk id = r&7). XOR float4 swizzle key=r&7 is
// conflict-free at 256B row stride (stride/16 = 0 mod 8). WARM=64 = 1 tile.

#define WARM  64
#define TSZ   64            // timesteps per tile

__device__ __forceinline__ float ex2_approx(float v) {
    float y; asm("ex2.approx.f32 %0, %1;" : "=f"(y) : "f"(v)); return y;
}
__device__ __forceinline__ float rcp_approx(float v) {
    float y; asm("rcp.approx.f32 %0, %1;" : "=f"(y) : "f"(v)); return y;
}

// sigma_tilde = -2*log2(e)*sigma = K1*(z - z^2) + K2*x
#define K1 (-10.098865286222744f)  /* -7 * log2(e) */
#define K2 (-1.4426950408889634f)  /* -1 * log2(e) */

__device__ __forceinline__ float step_z(float z, float xx) {
    float p  = fmaf(-z, z, z);          // z - z^2
    float tt = fmaf(K1, p, K2 * xx);
    float e  = ex2_approx(tt);
    float r  = rcp_approx(1.0f + e);    // sigmoid(2*sigma)
    return fmaf(0.5f, r, 0.5f * z);
}

__device__ __forceinline__ void cpasync16(uint32_t s, const void* g) {
    asm volatile("cp.async.cg.shared.global [%0], [%1], 16;" :: "r"(s), "l"(g));
}
#define CP_COMMIT() asm volatile("cp.async.commit_group;" ::: "memory")
#define CP_WAIT0()  asm volatile("cp.async.wait_group 0;"  ::: "memory")

__global__ void __launch_bounds__(128, 7)
chaos_kernel(const float* __restrict__ x,
             const float* __restrict__ z0,
             float* __restrict__ u,
             int n_ch, int T)
{
    // Per-warp slab: 32 rows x 16 float4 (256B row stride) = 8KB; 32KB/block.
    __shared__ float4 sbuf[4][32][16];

    const int tid  = threadIdx.x;
    const int wid  = tid >> 5;
    const int lane = tid & 31;

    const int CHUNK = T >> 3;                 // 512 (S = 8 chunks)
    const int NT    = CHUNK / TSZ;            // 8 tiles

    // Warp owns channels [ch0, ch0+4): one contiguous 64KB span of x.
    const int ch0 = blockIdx.x * 16 + wid * 4;
    const char* __restrict__ gx = (const char*)(x + (size_t)ch0 * T);
    char* __restrict__       gu = (char*)(u + (size_t)ch0 * T);

    const int l3 = lane >> 3;                 // 0..3  (loader row group)
    const int c4 = lane & 7;                  // float4 column group (low half)

    float4 (*sb)[16] = sbuf[wid];
    const uint32_t slab = (uint32_t)__cvta_generic_to_shared(&sb[0][0]);

    // Loader: iteration j (0..15): jr=j&7 selects row r=l3+4*jr,
    // jh=j>>3 selects 128B column half. key = r&7 = l3|((j&1)<<2).
    //   gmem: off0 + jr*8192 + jh*128      (contiguous 128B per 8 lanes)
    //   smem: r*256 + ((c4^key)<<4) + jh*128
    const uint32_t off0 = (uint32_t)((l3 * CHUNK + c4 * 4) * 4);
    const uint32_t JSTR = (uint32_t)(4 * CHUNK * 4);   // 8192

    // Compute role: row = lane, channel = ch0 + l3, chunk s = lane&7.
    const int s    = lane & 7;
    const int ckey = lane & 7;
    float z = (s == 0) ? z0[ch0 + l3] : 0.5f;

    // ---- Warmup: one tile of 64 steps (chunk-0 rows skip) ----
    {
        const int tb = -WARM * 4;                     // byte offset in t
#pragma unroll
        for (int j = 0; j < 16; ++j) {
            int jr = j & 7, jh = j >> 3;
            int r  = l3 + 4 * jr;
            int key = l3 | ((j & 1) << 2);
            if (key != 0) {
                uint32_t soff = (uint32_t)(r * 256 + ((c4 ^ key) << 4) + jh * 128);
                cpasync16(slab + soff, gx + off0 + tb + jr * JSTR + jh * 128);
            }
        }
        CP_COMMIT(); CP_WAIT0();
        __syncwarp();
        if (s != 0) {
#pragma unroll
            for (int c = 0; c < 16; ++c) {
                float4 v = sb[lane][c ^ ckey];
                z = step_z(z, v.x); z = step_z(z, v.y);
                z = step_z(z, v.z); z = step_z(z, v.w);
            }
        }
        __syncwarp();
    }

    // ---- Main: per-tile cp.async load -> compute in place -> store ----
    for (int tile = 0; tile < NT; ++tile) {
        const uint32_t tb = (uint32_t)(tile * TSZ * 4);

#pragma unroll
        for (int j = 0; j < 16; ++j) {
            int jr = j & 7, jh = j >> 3;
            int r  = l3 + 4 * jr;
            int key = l3 | ((j & 1) << 2);
            uint32_t soff = (uint32_t)(r * 256 + ((c4 ^ key) << 4) + jh * 128);
            cpasync16(slab + soff, gx + off0 + tb + jr * JSTR + jh * 128);
        }
        CP_COMMIT(); CP_WAIT0();
        __syncwarp();

        // Compute in place: x tile -> u tile (own row only)
#pragma unroll
        for (int c = 0; c < 16; ++c) {
            float4 v = sb[lane][c ^ ckey];
            float4 o; float h;
            h = fmaf(0.5f, v.x, -0.5f); z = step_z(z, v.x); o.x = h + z;
            h = fmaf(0.5f, v.y, -0.5f); z = step_z(z, v.y); o.y = h + z;
            h = fmaf(0.5f, v.z, -0.5f); z = step_z(z, v.z); o.z = h + z;
            h = fmaf(0.5f, v.w, -0.5f); z = step_z(z, v.w); o.w = h + z;
            sb[lane][c ^ ckey] = o;
        }
        __syncwarp();

        // Coalesced store-out
#pragma unroll
        for (int j = 0; j < 16; ++j) {
            int jr = j & 7, jh = j >> 3;
            int r  = l3 + 4 * jr;
            int key = l3 | ((j & 1) << 2);
            float4 v = sb[r][(c4 ^ key) | (jh << 3)];
            *(float4*)(gu + off0 + tb + jr * JSTR + jh * 128) = v;
        }
        __syncwarp();                        // slab safe before next cp.async
    }
}

extern "C" void kernel_launch(void* const* d_in, const int* in_sizes, int n_in,
                              void* d_out, int out_size)
{
    const float* x  = (const float*)d_in[0];   // (b, c, t) f32
    const float* z0 = (const float*)d_in[1];   // (b, c)    f32
    float* u = (float*)d_out;

    int n_ch = in_sizes[1];            // b*c = 16384
    int T    = in_sizes[0] / n_ch;     // 4096

    int grid = n_ch / 16;              // 16 channels per 128-thread block
    chaos_kernel<<<grid, 128>>>(x, z0, u, n_ch, T);
}

// round 16
// speedup vs baseline: 1.5182x; 1.0231x over previous
#include <cuda_runtime.h>
#include <cuda_bf16.h>
#include <cstdint>

// ChaosModulator: per-channel nonlinear recurrence over t.
//   sigma = 3.5*z*(1-z) + 0.5*x
//   z'    = 0.5*z + 0.5*sigmoid(2*sigma)     (clip(0,1) is a provable no-op)
//   u     = 0.5*x + (z' - 0.5)
//
// R16 = R13's warp-private cp.async double-buffer pipeline repackaged into
// 64-thread blocks. R13/R15 regressions were confounded by wave quantization:
// 33KB smem -> 6 blocks/SM -> grid 1024 = 1.15 waves, a 136-block straggler
// tail. Here: 2 warps/block, 16KB smem -> 13 blocks/SM, grid 2048 = 1.06
// waves (tiny, fast-draining tail), ~26 warps/SM like R10. launch_bounds
// (64,13) -> 78-reg cap, fits the pipeline's 72.
// Structure: S=8 chunks of 512, WARM=64 from z=0.5 (contraction), warp owns
// 4 channels x 8 chunks = 32 rows = contiguous 64KB x-span. Tile t+1 streams
// via cp.async into the idle slab during compute+store of tile t
// (wait_group 1). XOR float4 swizzle; __syncwarp only.

#define WARM  64
#define TS    32

__device__ __forceinline__ float ex2_approx(float v) {
    float y; asm("ex2.approx.f32 %0, %1;" : "=f"(y) : "f"(v)); return y;
}
__device__ __forceinline__ float rcp_approx(float v) {
    float y; asm("rcp.approx.f32 %0, %1;" : "=f"(y) : "f"(v)); return y;
}

// sigma_tilde = -2*log2(e)*sigma = K1*(z - z^2) + K2*x
#define K1 (-10.098865286222744f)  /* -7 * log2(e) */
#define K2 (-1.4426950408889634f)  /* -1 * log2(e) */

__device__ __forceinline__ float step_z(float z, float xx) {
    float p  = fmaf(-z, z, z);          // z - z^2
    float tt = fmaf(K1, p, K2 * xx);
    float e  = ex2_approx(tt);
    float r  = rcp_approx(1.0f + e);    // sigmoid(2*sigma)
    return fmaf(0.5f, r, 0.5f * z);
}

__device__ __forceinline__ void cpasync16(uint32_t s, const void* g) {
    asm volatile("cp.async.cg.shared.global [%0], [%1], 16;" :: "r"(s), "l"(g));
}
#define CP_COMMIT() asm volatile("cp.async.commit_group;" ::: "memory")
#define CP_WAIT0()  asm volatile("cp.async.wait_group 0;"  ::: "memory")
#define CP_WAIT1()  asm volatile("cp.async.wait_group 1;"  ::: "memory")

__global__ void __launch_bounds__(64, 13)
chaos_kernel(const float* __restrict__ x,
             const float* __restrict__ z0,
             float* __restrict__ u,
             int n_ch, int T)
{
    // Per-warp: 2 slabs of 32 rows x 8 float4 (128B row stride). 16KB/block.
    __shared__ float4 sbuf[2][2][32][8];

    const int tid  = threadIdx.x;
    const int wid  = tid >> 5;               // 0..1
    const int lane = tid & 31;

    const int CHUNK = T >> 3;                 // 512 (S = 8 chunks)
    const int NT    = CHUNK / TS;             // 16 tiles

    // Warp owns channels [ch0, ch0+4): one contiguous 64KB span of x.
    const int ch0 = blockIdx.x * 8 + wid * 4;
    const char* __restrict__ gx = (const char*)(x + (size_t)ch0 * T);
    char* __restrict__       gu = (char*)(u + (size_t)ch0 * T);

    const int l3 = lane >> 3;                 // 0..3  (loader row group)
    const int c4 = lane & 7;                  // float4 column group

    float4 (*sb0)[8] = sbuf[wid][0];
    float4 (*sb1)[8] = sbuf[wid][1];

    const uint32_t slab0 = (uint32_t)__cvta_generic_to_shared(&sb0[0][0]);
    const uint32_t slab1 = slab0 + 32 * 8 * 16;       // +4096

    // Loader smem offset for row r = l3 + 4j, swizzle key = r&7 = l3|4(j&1):
    //   soff(j) = l3*128 + j*512 + ( ((c4^l3) ^ ((j&1)<<2)) << 4 )
    const uint32_t lrow = (uint32_t)(l3 * 128);
    const uint32_t lcol = (uint32_t)(c4 ^ l3);

    // Gmem byte offset: row l3 base; +4 rows per j => +4*CHUNK floats.
    const uint32_t off0 = (uint32_t)((l3 * CHUNK + c4 * 4) * 4);
    const uint32_t JSTR = (uint32_t)(4 * CHUNK * 4);  // 8192

    // Compute role: row = lane, channel = ch0 + l3, chunk s = lane&7.
    const int s    = lane & 7;
    const int ckey = lane & 7;
    float z = (s == 0) ? z0[ch0 + l3] : 0.5f;

    // ---- Warmup: 2 tiles of 32 steps via slab0 (chunk-0 rows skip) ----
    for (int w = 0; w < WARM / TS; ++w) {
        const int tb = (-WARM + w * TS) * 4;          // byte offset in t
#pragma unroll
        for (int j = 0; j < 8; ++j) {
            int key = l3 | ((j & 1) << 2);            // r&7 for r=l3+4j
            uint32_t soff = lrow + j * 512 + ((lcol ^ ((j & 1) << 2)) << 4);
            if (key != 0)
                cpasync16(slab0 + soff, gx + off0 + tb + j * JSTR);
        }
        CP_COMMIT(); CP_WAIT0();
        __syncwarp();
        if (s != 0) {
#pragma unroll
            for (int c = 0; c < 8; ++c) {
                float4 v = sb0[lane][c ^ ckey];
                z = step_z(z, v.x); z = step_z(z, v.y);
                z = step_z(z, v.z); z = step_z(z, v.w);
            }
        }
        __syncwarp();
    }

    // ---- Prologue: tile 0 -> slab0 ----
#pragma unroll
    for (int j = 0; j < 8; ++j) {
        uint32_t soff = lrow + j * 512 + ((lcol ^ ((j & 1) << 2)) << 4);
        cpasync16(slab0 + soff, gx + off0 + j * JSTR);
    }
    CP_COMMIT();

    // ---- Main pipeline: prefetch t+1 while computing/storing t ----
    uint32_t curs = slab0, nxts = slab1;
    for (int tile = 0; tile < NT; ++tile) {
        const uint32_t tb = (uint32_t)(tile * TS * 4);

        if (tile + 1 < NT) {
            const uint32_t tb1 = tb + TS * 4;
#pragma unroll
            for (int j = 0; j < 8; ++j) {
                uint32_t soff = lrow + j * 512 + ((lcol ^ ((j & 1) << 2)) << 4);
                cpasync16(nxts + soff, gx + off0 + tb1 + j * JSTR);
            }
            CP_COMMIT();
            CP_WAIT1();                  // tile t landed; t+1 in flight
        } else {
            CP_WAIT0();                  // last tile: wait it fully
        }
        __syncwarp();

        // Compute in place: x tile -> u tile (own row only)
        {
            float4 (*bb)[8] = (curs == slab0) ? sb0 : sb1;
#pragma unroll
            for (int c = 0; c < 8; ++c) {
                float4 v = bb[lane][c ^ ckey];
                float4 o; float h;
                h = fmaf(0.5f, v.x, -0.5f); z = step_z(z, v.x); o.x = h + z;
                h = fmaf(0.5f, v.y, -0.5f); z = step_z(z, v.y); o.y = h + z;
                h = fmaf(0.5f, v.z, -0.5f); z = step_z(z, v.z); o.z = h + z;
                h = fmaf(0.5f, v.w, -0.5f); z = step_z(z, v.w); o.w = h + z;
                bb[lane][c ^ ckey] = o;
            }
        }
        __syncwarp();

        // Coalesced store-out of tile t
        {
            float4 (*bb)[8] = (curs == slab0) ? sb0 : sb1;
#pragma unroll
            for (int j = 0; j < 8; ++j) {
                int r   = l3 + 4 * j;
                int key = l3 | ((j & 1) << 2);
                float4 v = bb[r][c4 ^ key];
                *(float4*)(gu + off0 + tb + j * JSTR) = v;
            }
        }
        __syncwarp();   // all store-reads of this slab done before the
                        // cp.async issued next iteration overwrites it

        uint32_t tmp = curs; curs = nxts; nxts = tmp;
    }
}

extern "C" void kernel_launch(void* const* d_in, const int* in_sizes, int n_in,
                              void* d_out, int out_size)
{
    const float* x  = (const float*)d_in[0];   // (b, c, t) f32
    const float* z0 = (const float*)d_in[1];   // (b, c)    f32
    float* u = (float*)d_out;

    int n_ch = in_sizes[1];            // b*c = 16384
    int T    = in_sizes[0] / n_ch;     // 4096

    int grid = n_ch / 8;               // 8 channels per 64-thread block
    chaos_kernel<<<grid, 64>>>(x, z0, u, n_ch, T);
}

// round 17
// speedup vs baseline: 1.6437x; 1.0827x over previous
#include <cuda_runtime.h>
#include <cuda_bf16.h>
#include <cstdint>

// ChaosModulator: per-channel nonlinear recurrence over t.
//   sigma = 3.5*z*(1-z) + 0.5*x
//   z'    = 0.5*z + 0.5*sigmoid(2*sigma)     (clip(0,1) is a provable no-op)
//   u     = 0.5*x + (z' - 0.5)
//
// R17 = R10 (best: 100.4us) + streaming stores. Structural alternatives all
// falsified across R11-R16 (more warps / ILP-2 / cp.async in any packaging).
// u is write-once: st.global.cs (evict-first) keeps L2 from churning 256MB
// of output through it, preserving x tail-lines for the warmup re-reads and
// avoiding write-allocate pollution.
// Structure: S=8 chunks of 512, WARM=64 from z=0.5 (contraction erases
// state), warp owns 4 channels x 8 chunks = 32 rows = one contiguous 64KB
// x-span (addr = row*CHUNK + t, T = 8*CHUNK). 3-phase per 32-step tile:
// coalesced LDG -> swizzled STS -> compute in place -> coalesced STG.
// XOR float4 swizzle (c4 ^ (r&7), 128B rows) -> conflict-free. __syncwarp
// only; 32-bit byte-offset addressing keeps regs at 48.

#define WARM  64
#define TS    32

__device__ __forceinline__ float ex2_approx(float v) {
    float y; asm("ex2.approx.f32 %0, %1;" : "=f"(y) : "f"(v)); return y;
}
__device__ __forceinline__ float rcp_approx(float v) {
    float y; asm("rcp.approx.f32 %0, %1;" : "=f"(y) : "f"(v)); return y;
}

// sigma_tilde = -2*log2(e)*sigma = K1*(z - z^2) + K2*x
#define K1 (-10.098865286222744f)  /* -7 * log2(e) */
#define K2 (-1.4426950408889634f)  /* -1 * log2(e) */

__device__ __forceinline__ float step_z(float z, float xx) {
    float p  = fmaf(-z, z, z);          // z - z^2
    float tt = fmaf(K1, p, K2 * xx);
    float e  = ex2_approx(tt);
    float r  = rcp_approx(1.0f + e);    // sigmoid(2*sigma)
    return fmaf(0.5f, r, 0.5f * z);
}

__device__ __forceinline__ void stcs4(void* p, float4 v) {
    asm volatile("st.global.cs.v4.f32 [%0], {%1, %2, %3, %4};"
                 :: "l"(p), "f"(v.x), "f"(v.y), "f"(v.z), "f"(v.w)
                 : "memory");
}

__global__ void __launch_bounds__(128, 10)
chaos_kernel(const float* __restrict__ x,
             const float* __restrict__ z0,
             float* __restrict__ u,
             int n_ch, int T)
{
    // Per-warp slab: 32 rows x 8 float4 (128B row stride).
    __shared__ float4 sbuf[4][32][8];

    const int tid  = threadIdx.x;
    const int wid  = tid >> 5;
    const int lane = tid & 31;

    const int CHUNK = T >> 3;                 // 512 (S = 8 chunks)
    const int NT    = CHUNK / TS;             // 16 tiles

    // Warp owns channels [ch0, ch0+4): one contiguous 64KB span of x.
    const int ch0 = blockIdx.x * 16 + wid * 4;
    const char* __restrict__ gx = (const char*)(x + (size_t)ch0 * T);
    char* __restrict__       gu = (char*)(u + (size_t)ch0 * T);

    const int l3 = lane >> 3;                 // 0..3  (loader row group)
    const int c4 = lane & 7;                  // float4 column group

    float4 (*sb)[8] = sbuf[wid];

    // Loader base byte-offset for row l3 (+ j*4 rows => + j*8192 bytes).
    const uint32_t off0 = (uint32_t)((l3 * CHUNK + c4 * 4) * 4);
    const uint32_t JSTR = (uint32_t)(4 * CHUNK * 4);   // 8192 for CHUNK=512

    // Compute role: row = lane, channel = ch0 + l3, chunk s = lane&7.
    const int s    = lane & 7;
    const int ckey = lane & 7;
    float z = (s == 0) ? z0[ch0 + l3] : 0.5f;

    // ---- Warmup: 2 tiles of 32 steps (chunk-0 rows skip) ----
    for (int w = 0; w < WARM / TS; ++w) {
        const int tb = (-WARM + w * TS) * 4;          // byte offset in t
        uint32_t off = off0;
#pragma unroll
        for (int j = 0; j < 8; ++j, off += JSTR) {
            int key = l3 | ((j & 1) << 2);            // (r&7) for r=l3+4j
            if (key != 0) {
                float4 v = *(const float4*)(gx + off + tb);
                sb[l3 + 4 * j][c4 ^ key] = v;
            }
        }
        __syncwarp();
        if (s != 0) {
#pragma unroll
            for (int c = 0; c < 8; ++c) {
                float4 v = sb[lane][c ^ ckey];
                z = step_z(z, v.x); z = step_z(z, v.y);
                z = step_z(z, v.z); z = step_z(z, v.w);
            }
        }
        __syncwarp();
    }

    // ---- Main: per-tile load -> compute in place -> store, warp-private ----
    for (int tile = 0; tile < NT; ++tile) {
        const uint32_t tb = (uint32_t)(tile * TS * 4);

        {
            uint32_t off = off0 + tb;
#pragma unroll
            for (int j = 0; j < 8; ++j, off += JSTR) {
                int key = l3 | ((j & 1) << 2);
                float4 v = *(const float4*)(gx + off);
                sb[l3 + 4 * j][c4 ^ key] = v;
            }
        }
        __syncwarp();

#pragma unroll
        for (int c = 0; c < 8; ++c) {
            float4 v = sb[lane][c ^ ckey];
            float4 o; float h;
            h = fmaf(0.5f, v.x, -0.5f); z = step_z(z, v.x); o.x = h + z;
            h = fmaf(0.5f, v.y, -0.5f); z = step_z(z, v.y); o.y = h + z;
            h = fmaf(0.5f, v.z, -0.5f); z = step_z(z, v.z); o.z = h + z;
            h = fmaf(0.5f, v.w, -0.5f); z = step_z(z, v.w); o.w = h + z;
            sb[lane][c ^ ckey] = o;
        }
        __syncwarp();

        {
            uint32_t off = off0 + tb;
#pragma unroll
            for (int j = 0; j < 8; ++j, off += JSTR) {
                int key = l3 | ((j & 1) << 2);
                float4 v = sb[l3 + 4 * j][c4 ^ key];
                stcs4(gu + off, v);            // evict-first streaming store
            }
        }
        __syncwarp();                        // protect smem before next STS
    }
}

extern "C" void kernel_launch(void* const* d_in, const int* in_sizes, int n_in,
                              void* d_out, int out_size)
{
    const float* x  = (const float*)d_in[0];   // (b, c, t) f32
    const float* z0 = (const float*)d_in[1];   // (b, c)    f32
    float* u = (float*)d_out;

    int n_ch = in_sizes[1];            // b*c = 16384
    int T    = in_sizes[0] / n_ch;     // 4096

    int grid = n_ch / 16;              // 16 channels per 128-thread block
    chaos_kernel<<<grid, 128>>>(x, z0, u, n_ch, T);
}